// round 3
// baseline (speedup 1.0000x reference)
#include <cuda_runtime.h>
#include <cstdint>
#include <cstddef>

// RNN_49297634623576: out = fc_w @ tanh(w_ih @ x[:,27,:] + b_ih + b_hh) + fc_b
// hx == 0 => w_hh unused.
//
// R3 vs R2: same RPT=2/TPB=128 shape, restructured for ILP + fewer LDS:
//  - 2-j groups -> 4 independent layer-1 FFMA2 chains (saturates fma pipe).
//  - k-packed FC: acc = {out_2q, out_2q+1}; fc weights pre-packed k-pairs in
//    shared -> 5 LDS.64/j (was 10), 10 independent FC chains.
//  - biases folded into accumulator init ({b_j,0} / {fcb_2q,fcb_2q+1}) ->
//    no bias LDS in loop, no epilogue adds.

#define NB   65536
#define NIN  28
#define NHID 64
#define NOUT 10
#define RPT  2
#define TPB  128   // 256 rows/CTA -> 256 CTAs

typedef unsigned long long u64;

__device__ __forceinline__ u64 pk2(float a, float b) {
    u64 r; asm("mov.b64 %0,{%1,%2};" : "=l"(r) : "f"(a), "f"(b)); return r;
}
__device__ __forceinline__ void upk2(u64 v, float& a, float& b) {
    asm("mov.b64 {%0,%1},%2;" : "=f"(a), "=f"(b) : "l"(v));
}
__device__ __forceinline__ u64 ffma2(u64 a, u64 b, u64 c) {
    u64 d; asm("fma.rn.f32x2 %0,%1,%2,%3;" : "=l"(d) : "l"(a), "l"(b), "l"(c)); return d;
}
__device__ __forceinline__ float hsum2(u64 v) {
    float a, b; upk2(v, a, b); return a + b;
}

// tanh(x) = 1 - 2*rcp(exp2(x*2log2e)+1); FMUL, MUFU.EX2, FADD, MUFU.RCP, FFMA.
__device__ __forceinline__ float tanh_fast(float x) {
    const float LOG2E_X2 = 2.8853900817779268f;
    float e, r;
    asm("ex2.approx.ftz.f32 %0, %1;" : "=f"(e) : "f"(x * LOG2E_X2));
    asm("rcp.approx.ftz.f32 %0, %1;" : "=f"(r) : "f"(e + 1.0f));
    return fmaf(-2.0f, r, 1.0f);
}

__global__ void __launch_bounds__(TPB, 2)
rnn_fused_kernel(const float* __restrict__ x,
                 const float* __restrict__ w_ih,
                 const float* __restrict__ b_ih,
                 const float* __restrict__ b_hh,
                 const float* __restrict__ fc_w,
                 const float* __restrict__ fc_b,
                 float* __restrict__ out)
{
    __shared__ u64 s_w[NHID][NIN / 2];   // {w[j][2p], w[j][2p+1]}
    __shared__ u64 s_bp[NHID];           // {b_ih[j]+b_hh[j], 0}
    __shared__ u64 s_fck[NHID][NOUT/2];  // {fc_w[2q][j], fc_w[2q+1][j]}
    __shared__ u64 s_fcbp[NOUT / 2];     // {fc_b[2q], fc_b[2q+1]}

    const int tid = threadIdx.x;

    for (int i = tid; i < NHID * (NIN / 2); i += TPB) {
        int j = i / (NIN / 2), p = i % (NIN / 2);
        s_w[j][p] = pk2(w_ih[j * NIN + 2 * p], w_ih[j * NIN + 2 * p + 1]);
    }
    for (int i = tid; i < NHID; i += TPB) s_bp[i] = pk2(b_ih[i] + b_hh[i], 0.0f);
    for (int i = tid; i < NHID * (NOUT / 2); i += TPB) {
        int j = i / (NOUT / 2), q = i % (NOUT / 2);
        s_fck[j][q] = pk2(fc_w[(2 * q) * NHID + j], fc_w[(2 * q + 1) * NHID + j]);
    }
    if (tid < NOUT / 2) s_fcbp[tid] = pk2(fc_b[2 * tid], fc_b[2 * tid + 1]);
    __syncthreads();

    const int base = (blockIdx.x * TPB + tid) * RPT;

    // Last input row (28 floats) for 2 rows; float offset 756 is 16B aligned.
    u64 in0[NIN / 2], in1[NIN / 2];
    {
        const float4* p0 = reinterpret_cast<const float4*>(x + (size_t)base * 784 + 756);
        const float4* p1 = reinterpret_cast<const float4*>(x + (size_t)(base + 1) * 784 + 756);
#pragma unroll
        for (int q = 0; q < 7; q++) {
            float4 v0 = p0[q], v1 = p1[q];
            in0[2 * q]     = pk2(v0.x, v0.y);
            in0[2 * q + 1] = pk2(v0.z, v0.w);
            in1[2 * q]     = pk2(v1.x, v1.y);
            in1[2 * q + 1] = pk2(v1.z, v1.w);
        }
    }

    // FC accumulators: oa{r}[q] = {out[2q], out[2q+1]} for row r; bias pre-folded.
    u64 oa0[NOUT / 2], oa1[NOUT / 2];
#pragma unroll
    for (int q = 0; q < NOUT / 2; q++) { oa0[q] = s_fcbp[q]; oa1[q] = s_fcbp[q]; }

#pragma unroll 1
    for (int jj = 0; jj < NHID; jj += 2) {
        // 4 independent layer-1 chains: (j0,row0) (j0,row1) (j1,row0) (j1,row1)
        u64 b0 = s_bp[jj], b1 = s_bp[jj + 1];
        u64 a00 = b0, a01 = b0, a10 = b1, a11 = b1;
#pragma unroll
        for (int p = 0; p < NIN / 2; p++) {
            u64 w0 = s_w[jj][p];
            u64 w1 = s_w[jj + 1][p];
            a00 = ffma2(w0, in0[p], a00);
            a01 = ffma2(w0, in1[p], a01);
            a10 = ffma2(w1, in0[p], a10);
            a11 = ffma2(w1, in1[p], a11);
        }
        float h00 = tanh_fast(hsum2(a00));  // row0, j0
        float h01 = tanh_fast(hsum2(a01));  // row1, j0
        float h10 = tanh_fast(hsum2(a10));  // row0, j1
        float h11 = tanh_fast(hsum2(a11));  // row1, j1
        u64 hp00 = pk2(h00, h00);
        u64 hp01 = pk2(h01, h01);
        u64 hp10 = pk2(h10, h10);
        u64 hp11 = pk2(h11, h11);
        // FC: 10 independent chains, 2 FFMA2 each per group, 10 LDS.64 total.
#pragma unroll
        for (int q = 0; q < NOUT / 2; q++) {
            u64 f0 = s_fck[jj][q];
            u64 f1 = s_fck[jj + 1][q];
            oa0[q] = ffma2(f0, hp00, oa0[q]);
            oa1[q] = ffma2(f0, hp01, oa1[q]);
            oa0[q] = ffma2(f1, hp10, oa0[q]);
            oa1[q] = ffma2(f1, hp11, oa1[q]);
        }
    }

    // Store: 5 STG.64 per row (rows are 8B-aligned: 10 floats = 40B stride).
    {
        float2* o0 = reinterpret_cast<float2*>(out + (size_t)base * NOUT);
        float2* o1 = reinterpret_cast<float2*>(out + (size_t)(base + 1) * NOUT);
#pragma unroll
        for (int q = 0; q < NOUT / 2; q++) {
            float a, b;
            upk2(oa0[q], a, b);
            o0[q] = make_float2(a, b);
            upk2(oa1[q], a, b);
            o1[q] = make_float2(a, b);
        }
    }
}

extern "C" void kernel_launch(void* const* d_in, const int* in_sizes, int n_in,
                              void* d_out, int out_size)
{
    (void)in_sizes; (void)n_in; (void)out_size;
    const float* x    = (const float*)d_in[0];
    const float* w_ih = (const float*)d_in[1];
    // d_in[2] = w_hh : unused (hx == 0)
    const float* b_ih = (const float*)d_in[3];
    const float* b_hh = (const float*)d_in[4];
    const float* fc_w = (const float*)d_in[5];
    const float* fc_b = (const float*)d_in[6];
    float* out = (float*)d_out;

    const int blocks = NB / (TPB * RPT);   // 256, exact

    rnn_fused_kernel<<<blocks, TPB>>>(x, w_ih, b_ih, b_hh, fc_w, fc_b, out);
}